// round 17
// baseline (speedup 1.0000x reference)
#include <cuda_runtime.h>

#define BATCH   8
#define NDATA   8192
#define NPOINT  1024
#define NSAMPLE 32
#define CFEAT   64
#define RADIUSF 0.2f

#define NP_SIZE  (BATCH*NPOINT*NSAMPLE*(3+CFEAT))   /* 17563648 */
#define IDX_OFF  NP_SIZE
#define IDX_SIZE (BATCH*NPOINT*NSAMPLE)             /* 262144 */
#define GX_OFF   (IDX_OFF + IDX_SIZE)

#define QB  16   /* queries per block (2 per warp) */
#define WPB 8
#define CAP 64   /* candidate capacity per query  */

/* uniform grid */
#define NCD     34
#define NCELLB  (NCD*NCD*NCD)                       /* 39304 */
#define NCELLS  (BATCH*NCELLB)                      /* 314432 */
#define CAPC    64
#define CS      0.25f
#define INV_CS  4.0f
#define GLO     (-4.25f)
#define RPAD    0.2005f

__device__ float4 g_pts[BATCH*NDATA];               /* (x,y,z,|p|^2) */
__device__ int    g_ccnt[NCELLS];
__device__ int    g_bucket[NCELLS*CAPC];            /* ~80 MB static */

__global__ void k_zero()
{
    int t = blockIdx.x * blockDim.x + threadIdx.x;
    if (t < NCELLS) g_ccnt[t] = 0;
}

__global__ void k_build(const float* __restrict__ xyz)
{
    int t = blockIdx.x * blockDim.x + threadIdx.x;
    if (t >= BATCH*NDATA) return;
    float x = xyz[3*t + 0];
    float y = xyz[3*t + 1];
    float z = xyz[3*t + 2];
    g_pts[t] = make_float4(x, y, z, 0.0f);
    int b  = t >> 13;
    int cx = min(NCD-1, max(0, (int)floorf((x - GLO)*INV_CS)));
    int cy = min(NCD-1, max(0, (int)floorf((y - GLO)*INV_CS)));
    int cz = min(NCD-1, max(0, (int)floorf((z - GLO)*INV_CS)));
    int cell = b*NCELLB + (cx*NCD + cy)*NCD + cz;
    int slot = atomicAdd(&g_ccnt[cell], 1);
    if (slot < CAPC) g_bucket[cell*CAPC + slot] = t & (NDATA-1);
}

__global__ __launch_bounds__(WPB*32, 6)
void k_search(const float* __restrict__ new_xyz,
              const float* __restrict__ points,
              float* __restrict__ out)
{
    __shared__ float s_cd[QB][CAP];
    __shared__ int   s_ci[QB][CAP];
    __shared__ int   s_cnt[QB];
    __shared__ int   s_out[QB][NSAMPLE];

    const int b    = blockIdx.y;
    const int w    = threadIdx.x >> 5;
    const int lane = threadIdx.x & 31;
    const int p0   = blockIdx.x * QB;

    const float4* pts = g_pts + b*NDATA;
    const int bOff = b*NCELLB;

    if (lane < 2) s_cnt[w*2 + lane] = 0;
    __syncwarp();

    /* ---- per-warp grid scan for its 2 queries --------------------------- */
#pragma unroll
    for (int qq = 0; qq < 2; qq++) {
        const int q = w*2 + qq;
        const float* qp = new_xyz + ((size_t)b*NPOINT + p0 + q) * 3;
        const float cx = qp[0], cy = qp[1], cz = qp[2];

        int c0x = max(0,     (int)floorf((cx - RPAD - GLO)*INV_CS));
        int c1x = min(NCD-1, (int)floorf((cx + RPAD - GLO)*INV_CS));
        int c0y = max(0,     (int)floorf((cy - RPAD - GLO)*INV_CS));
        int c1y = min(NCD-1, (int)floorf((cy + RPAD - GLO)*INV_CS));
        int c0z = max(0,     (int)floorf((cz - RPAD - GLO)*INV_CS));
        int c1z = min(NCD-1, (int)floorf((cz + RPAD - GLO)*INV_CS));
        int ny = c1y - c0y + 1;
        int nz = c1z - c0z + 1;
        int ncell = (c1x - c0x + 1) * ny * nz;

        for (int l = lane; l < ncell; l += 32) {
            int iz = l % nz;
            int t2 = l / nz;
            int iy = t2 % ny;
            int ix = t2 / ny;
            int cell = bOff + ((c0x+ix)*NCD + (c0y+iy))*NCD + (c0z+iz);
            int cnt = min(g_ccnt[cell], CAPC);
            const int* bk = g_bucket + (size_t)cell*CAPC;
            for (int i = 0; i < cnt; i++) {
                int id = bk[i];
                float4 P = pts[id];
                /* exact reference arithmetic */
                float dx = P.x - cx;
                float dy = P.y - cy;
                float dz = P.z - cz;
                float e = __fadd_rn(__fadd_rn(__fmul_rn(dx,dx), __fmul_rn(dy,dy)),
                                    __fmul_rn(dz,dz));
                float d = __fsqrt_rn(e);
                if (d < RADIUSF) {
                    int slot = atomicAdd(&s_cnt[q], 1);
                    if (slot < CAP) { s_cd[q][slot] = d; s_ci[q][slot] = id; }
                }
            }
        }
    }
    __syncwarp();

    /* ---- rank + gather: warp-local, no block barriers ------------------- */
#pragma unroll
    for (int qq = 0; qq < 2; qq++) {
        const int q = w*2 + qq;
        const int n = min(s_cnt[q], CAP);
        const size_t R0 = ((size_t)b*NPOINT + p0 + q) * NSAMPLE;

        if (n == 0) {
            /* rare: warp-local global argmin rescan */
            const float* qp = new_xyz + ((size_t)b*NPOINT + p0 + q) * 3;
            const float cx = qp[0], cy = qp[1], cz = qp[2];
            float bd = 3.4e38f; int bi = 0;
            for (int pt = lane; pt < NDATA; pt += 32) {
                float4 P = pts[pt];
                float dx = P.x - cx;
                float dy = P.y - cy;
                float dz = P.z - cz;
                float e  = __fadd_rn(__fadd_rn(__fmul_rn(dx,dx), __fmul_rn(dy,dy)),
                                     __fmul_rn(dz,dz));
                if (e < bd) { bd = e; bi = pt; }
            }
#pragma unroll
            for (int off = 16; off >= 1; off >>= 1) {
                float od = __shfl_xor_sync(0xffffffffu, bd, off);
                int   oi = __shfl_xor_sync(0xffffffffu, bi, off);
                if (od < bd || (od == bd && oi < bi)) { bd = od; bi = oi; }
            }
            s_out[q][lane] = bi;
        } else {
            for (int i = lane; i < n; i += 32) {
                float di = s_cd[q][i]; int ii = s_ci[q][i];
                int rank = 0;
                for (int j = 0; j < n; j++) {
                    float dj = s_cd[q][j]; int ij = s_ci[q][j];
                    rank += (dj < di) || (dj == di && ij < ii);
                }
                if (rank < NSAMPLE) s_out[q][rank] = ii;
            }
            __syncwarp();
            int nearest = s_out[q][0];
            if (lane >= n) s_out[q][lane] = nearest;
        }
        __syncwarp();

        out[IDX_OFF + R0 + lane] = (float)s_out[q][lane];

        /* gather this query's 32 rows: 4-row unroll, MLP=8 feature loads */
        const float* Pb  = points + (size_t)b*NDATA*CFEAT;
        float* onp = out + R0*67;
        float* ogx = out + GX_OFF + R0*3;

#pragma unroll
        for (int r0 = 0; r0 < NSAMPLE; r0 += 4) {
            int ids[4];
#pragma unroll
            for (int u = 0; u < 4; u++) ids[u] = s_out[q][r0 + u];

            float v0[4], v1[4];
#pragma unroll
            for (int u = 0; u < 4; u++) {
                v0[u] = __ldg(&Pb[ids[u]*CFEAT + lane]);
                v1[u] = __ldg(&Pb[ids[u]*CFEAT + 32 + lane]);
            }
#pragma unroll
            for (int u = 0; u < 4; u++) {
                onp[(r0 + u)*67 + 3  + lane] = v0[u];
                onp[(r0 + u)*67 + 35 + lane] = v1[u];
            }
            if (lane < 3) {
                float xv[4];
#pragma unroll
                for (int u = 0; u < 4; u++) {
                    float4 Q = __ldg(&pts[ids[u]]);        /* L1 broadcast */
                    xv[u] = (lane == 0) ? Q.x : ((lane == 1) ? Q.y : Q.z);
                }
#pragma unroll
                for (int u = 0; u < 4; u++) {
                    onp[(r0 + u)*67 + lane] = xv[u];
                    ogx[(r0 + u)*3  + lane] = xv[u];
                }
            }
        }
    }
}

extern "C" void kernel_launch(void* const* d_in, const int* in_sizes, int n_in,
                              void* d_out, int out_size)
{
    const float *new_xyz = nullptr, *xyz = nullptr, *points = nullptr;
    for (int i = 0; i < n_in; i++) {
        if      (in_sizes[i] == BATCH*NPOINT*3)     new_xyz = (const float*)d_in[i];
        else if (in_sizes[i] == BATCH*NDATA*3)      xyz     = (const float*)d_in[i];
        else if (in_sizes[i] == BATCH*NDATA*CFEAT)  points  = (const float*)d_in[i];
    }
    float* out = (float*)d_out;

    k_zero <<<(NCELLS + 1023)/1024, 1024>>>();
    k_build<<<(BATCH*NDATA + 255)/256, 256>>>(xyz);

    dim3 gs(NPOINT/QB, BATCH);
    k_search<<<gs, WPB*32>>>(new_xyz, points, out);
}